// round 13
// baseline (speedup 1.0000x reference)
#include <cuda_runtime.h>

#define TPB   512
#define DIM   4096
#define KSEL  409
#define NWARP (TPB / 32)
#define MAXC  512

// 256 exact power-of-two bins over (1.5, 2.0]: bin = (|x|-1.5)*512 via
// fma(|x|,512,-768), EXACT for |x| in (1.5,2) -> deterministic membership.
// >=2.0 saturates into overflow bin 255; top-down cumulative == count(|x| >= edge).
// Rows whose rank bin is not found below 255 take the generic bisection fallback.
//
// 512 threads x 8 elements: row stays REGISTER-resident (no smem staging),
// killing the 48KB/CTA L1 staging traffic of the 256-thread smem variant while
// holding 3 CTAs/SM (48 warps) via launch_bounds(512,3).
__global__ __launch_bounds__(TPB, 3) void sparsify_kernel(const float* __restrict__ x,
                                                          float* __restrict__ out) {
    __shared__ int      s_hist[256];
    __shared__ unsigned s_w[NWARP];
    __shared__ float    s_wf[NWARP];
    __shared__ float    s_memb[MAXC];
    __shared__ int      s_cnt;
    __shared__ int      s_selbin, s_need;
    __shared__ float    s_thr;

    const int t    = threadIdx.x;
    const int lane = t & 31;
    const int wid  = t >> 5;

    const float4* xr   = reinterpret_cast<const float4*>(x + (size_t)blockIdx.x * DIM);
    float4*       orow = reinterpret_cast<float4*>(out + (size_t)blockIdx.x * DIM);

    float4 v0 = xr[t];
    float4 v1 = xr[t + TPB];

    if (t < 256) s_hist[t] = 0;
    if (t == 0) { s_cnt = 0; s_selbin = 255; s_need = 1; s_thr = 1.645f; }
    __syncthreads();                                   // B1

    // ---- pass 1: one-pass exact histogram over 8 register values ----
    #define HC(e) { float d = fmaf(fabsf(e), 512.0f, -768.0f); \
                    int b = min(__float2int_rz(d), 255); \
                    if (d > 0.0f) atomicAdd(&s_hist[b], 1); }
    HC(v0.x) HC(v0.y) HC(v0.z) HC(v0.w)
    HC(v1.x) HC(v1.y) HC(v1.z) HC(v1.w)
    #undef HC
    __syncthreads();                                   // B2

    // ---- warp 0: top-down scan of 256 bins -> rank bin + local rank ----
    if (wid == 0) {
        const int base = 255 - 8 * lane;               // lane0: bins 255..248, ...
        int h[8]; int lsum = 0;
        #pragma unroll
        for (int k = 0; k < 8; k++) { h[k] = s_hist[base - k]; lsum += h[k]; }
        int cum = lsum;
        #pragma unroll
        for (int o = 1; o < 32; o <<= 1) {
            int n = __shfl_up_sync(0xFFFFFFFFu, cum, o);
            if (lane >= o) cum += n;
        }
        unsigned bal = __ballot_sync(0xFFFFFFFFu, cum >= KSEL);
        if (bal) {
            int L = __ffs(bal) - 1;
            if (lane == L) {
                int ca = cum - lsum;                   // count strictly above lane's bins
                int sel = 255, r = 1;
                #pragma unroll
                for (int k = 0; k < 8; k++) {
                    if (ca + h[k] >= KSEL) { sel = base - k; r = KSEL - ca; break; }
                    ca += h[k];
                }
                s_selbin = sel; s_need = r;
            }
        }
        // bal == 0 -> s_selbin stays 255 -> fallback
    }
    __syncthreads();                                   // B3

    const int sb = s_selbin;                           // uniform across CTA
    int nd;
    if (sb < 255) {
        // ---- gather rank-bin members from registers (identical bin recompute) ----
        nd = s_need;
        #define TG(e) { float d = fmaf(fabsf(e), 512.0f, -768.0f); \
                        if (d > 0.0f && __float2int_rz(d) == sb) { \
                            int id = atomicAdd(&s_cnt, 1); \
                            if (id < MAXC) s_memb[id] = fabsf(e); } }
        TG(v0.x) TG(v0.y) TG(v0.z) TG(v0.w)
        TG(v1.x) TG(v1.y) TG(v1.z) TG(v1.w)
        #undef TG
    } else {
        // ---- generic fallback: exact bisection over register values (~never) ----
        float m = fmaxf(fmaxf(fabsf(v0.x), fabsf(v0.y)), fmaxf(fabsf(v0.z), fabsf(v0.w)));
        m = fmaxf(m, fmaxf(fmaxf(fabsf(v1.x), fabsf(v1.y)), fmaxf(fabsf(v1.z), fabsf(v1.w))));
        #pragma unroll
        for (int o = 16; o; o >>= 1) m = fmaxf(m, __shfl_xor_sync(0xFFFFFFFFu, m, o));
        if (lane == 0) s_wf[wid] = m;
        __syncthreads();
        float maxv = s_wf[0];
        #pragma unroll
        for (int w = 1; w < NWARP; w++) maxv = fmaxf(maxv, s_wf[w]);
        __syncthreads();

        float lo = -1.0f, hi = maxv;
        int cLo = DIM, cHi = 0, guard = 0;
        while ((cLo - cHi) > (MAXC - 64) && guard < 40) {
            float mid = 0.5f * (lo + hi);
            if (!(mid > lo && mid < hi)) break;        // degenerate (ties)
            int cc = 0;
            cc += fabsf(v0.x) > mid; cc += fabsf(v0.y) > mid;
            cc += fabsf(v0.z) > mid; cc += fabsf(v0.w) > mid;
            cc += fabsf(v1.x) > mid; cc += fabsf(v1.y) > mid;
            cc += fabsf(v1.z) > mid; cc += fabsf(v1.w) > mid;
            unsigned r = __reduce_add_sync(0xFFFFFFFFu, (unsigned)cc);
            if (lane == 0) s_w[wid] = r;
            __syncthreads();
            unsigned tot = 0;
            #pragma unroll
            for (int w = 0; w < NWARP; w++) tot += s_w[w];
            __syncthreads();
            if ((int)tot >= KSEL) { lo = mid; cLo = (int)tot; }
            else                  { hi = mid; cHi = (int)tot; }
            guard++;
        }
        if (t == 0) s_cnt = 0;
        __syncthreads();
        #define TG2(e) { float av = fabsf(e); \
                         if (av > lo && av <= hi) { int id = atomicAdd(&s_cnt, 1); \
                             if (id < MAXC) s_memb[id] = av; } }
        TG2(v0.x) TG2(v0.y) TG2(v0.z) TG2(v0.w)
        TG2(v1.x) TG2(v1.y) TG2(v1.z) TG2(v1.w)
        #undef TG2
        nd = KSEL - cHi;
    }
    __syncthreads();                                   // B4

    // ---- exact select: nd-th largest among c members (typically c ~ 2-4) ----
    const int c = min(s_cnt, MAXC);
    for (int j = t; j < c; j += TPB) {
        float vj = s_memb[j];
        int gt = 0, ge = 0;
        for (int i = 0; i < c; i++) {
            float vi = s_memb[i];
            gt += vi > vj;
            ge += vi >= vj;
        }
        if (gt < nd && nd <= ge) s_thr = vj;           // matching writers write same value
    }
    __syncthreads();                                   // B5

    const float thr   = s_thr;
    const float bias5 = -5.0f * thr;

    // ---- fused epilogue: out = x * (0.5 + 0.5*tanh(5*(|x|-thr))) ----
    #define MK(dst, xv) { float z = fmaf(5.0f, fabsf(xv), bias5); float th; \
                          asm("tanh.approx.f32 %0, %1;" : "=f"(th) : "f"(z)); \
                          dst = (xv) * fmaf(0.5f, th, 0.5f); }
    float4 o0, o1;
    MK(o0.x, v0.x) MK(o0.y, v0.y) MK(o0.z, v0.z) MK(o0.w, v0.w)
    MK(o1.x, v1.x) MK(o1.y, v1.y) MK(o1.z, v1.z) MK(o1.w, v1.w)
    #undef MK
    orow[t]       = o0;
    orow[t + TPB] = o1;
}

extern "C" void kernel_launch(void* const* d_in, const int* in_sizes, int n_in,
                              void* d_out, int out_size) {
    const float* x = (const float*)d_in[0];
    float* out = (float*)d_out;
    const int rows = in_sizes[0] / DIM;   // 4 * 2048 = 8192 rows
    sparsify_kernel<<<rows, TPB>>>(x, out);
}

// round 14
// speedup vs baseline: 1.2426x; 1.2426x over previous
#include <cuda_runtime.h>

#define TPB   256
#define DIM   4096
#define KSEL  409
#define NWARP (TPB / 32)
#define MAXC  512

// 256 exact power-of-two bins over (1.5, 2.0]: bin = (|x|-1.5)*512 via
// fma(|x|,512,-768), EXACT for |x| in (1.5,2) -> deterministic membership.
// >=2.0 saturates into overflow bin 255; top-down cumulative == count(|x| >= edge).
// Rows whose rank bin is not found below 255 take the generic bisection fallback.
//
// NO smem row staging: pass 1 loads via plain LDG (allocates L1 lines); with
// only ~3.3KB smem/CTA the L1D carveout leaves ~200KB, and 8 CTAs x 16KB rows
// = 128KB stay L1-resident for the gather/epilogue re-reads. A per-thread
// 16-bit candidate mask (built from the d>0 predicate already computed in
// pass 1) lets the gather skip float4 groups with no candidate.
__global__ __launch_bounds__(TPB, 8) void sparsify_kernel(const float* __restrict__ x,
                                                          float* __restrict__ out) {
    __shared__ int      s_hist[256];
    __shared__ unsigned s_w[NWARP];
    __shared__ float    s_wf[NWARP];
    __shared__ float    s_memb[MAXC];
    __shared__ int      s_cnt;
    __shared__ int      s_selbin, s_need;
    __shared__ float    s_thr;

    const int t    = threadIdx.x;
    const int lane = t & 31;
    const int wid  = t >> 5;

    const float4* xr   = reinterpret_cast<const float4*>(x + (size_t)blockIdx.x * DIM);
    float4*       orow = reinterpret_cast<float4*>(out + (size_t)blockIdx.x * DIM);

    s_hist[t] = 0;
    if (t == 0) { s_cnt = 0; s_selbin = 255; s_need = 1; s_thr = 1.645f; }
    __syncthreads();                                   // B1

    // ---- pass 1: LDG (L1-allocating) -> exact histogram + candidate bitmask ----
    unsigned cmask = 0;
    #pragma unroll
    for (int u = 0; u < 4; u++) {
        float4 v = xr[t + u * TPB];
        #define HC(e, i) { float d = fmaf(fabsf(e), 512.0f, -768.0f); \
                           if (d > 0.0f) { \
                               int b = min(__float2int_rz(d), 255); \
                               atomicAdd(&s_hist[b], 1); \
                               cmask |= 1u << (4 * u + (i)); } }
        HC(v.x, 0) HC(v.y, 1) HC(v.z, 2) HC(v.w, 3)
        #undef HC
    }
    __syncthreads();                                   // B2

    // ---- warp 0: top-down scan of 256 bins -> rank bin + local rank ----
    if (wid == 0) {
        const int base = 255 - 8 * lane;               // lane0: bins 255..248, ...
        int h[8]; int lsum = 0;
        #pragma unroll
        for (int k = 0; k < 8; k++) { h[k] = s_hist[base - k]; lsum += h[k]; }
        int cum = lsum;
        #pragma unroll
        for (int o = 1; o < 32; o <<= 1) {
            int n = __shfl_up_sync(0xFFFFFFFFu, cum, o);
            if (lane >= o) cum += n;
        }
        unsigned bal = __ballot_sync(0xFFFFFFFFu, cum >= KSEL);
        if (bal) {
            int L = __ffs(bal) - 1;
            if (lane == L) {
                int ca = cum - lsum;                   // count strictly above lane's bins
                int sel = 255, r = 1;
                #pragma unroll
                for (int k = 0; k < 8; k++) {
                    if (ca + h[k] >= KSEL) { sel = base - k; r = KSEL - ca; break; }
                    ca += h[k];
                }
                s_selbin = sel; s_need = r;
            }
        }
        // bal == 0 -> s_selbin stays 255 -> fallback
    }
    __syncthreads();                                   // B3

    const int sb = s_selbin;                           // uniform across CTA
    int nd;
    if (sb < 255) {
        // ---- sparse gather: re-read (L1 hit) only groups holding candidates ----
        nd = s_need;
        #pragma unroll
        for (int u = 0; u < 4; u++) {
            unsigned g = (cmask >> (4 * u)) & 0xFu;
            if (g) {
                float4 v = xr[t + u * TPB];
                #define TG(e, i) if (g & (1u << (i))) { \
                        float d = fmaf(fabsf(e), 512.0f, -768.0f); \
                        if (__float2int_rz(d) == sb) { \
                            int id = atomicAdd(&s_cnt, 1); \
                            if (id < MAXC) s_memb[id] = fabsf(e); } }
                TG(v.x, 0) TG(v.y, 1) TG(v.z, 2) TG(v.w, 3)
                #undef TG
            }
        }
    } else {
        // ---- generic fallback: exact bisection, row re-read via L1/L2 (~never) ----
        float m = 0.0f;
        #pragma unroll
        for (int u = 0; u < 4; u++) {
            float4 v = xr[t + u * TPB];
            m = fmaxf(m, fmaxf(fmaxf(fabsf(v.x), fabsf(v.y)),
                               fmaxf(fabsf(v.z), fabsf(v.w))));
        }
        #pragma unroll
        for (int o = 16; o; o >>= 1) m = fmaxf(m, __shfl_xor_sync(0xFFFFFFFFu, m, o));
        if (lane == 0) s_wf[wid] = m;
        __syncthreads();
        float maxv = s_wf[0];
        #pragma unroll
        for (int w = 1; w < NWARP; w++) maxv = fmaxf(maxv, s_wf[w]);
        __syncthreads();

        float lo = -1.0f, hi = maxv;
        int cLo = DIM, cHi = 0, guard = 0;
        while ((cLo - cHi) > (MAXC - 64) && guard < 40) {
            float mid = 0.5f * (lo + hi);
            if (!(mid > lo && mid < hi)) break;        // degenerate (ties)
            int cc = 0;
            #pragma unroll
            for (int u = 0; u < 4; u++) {
                float4 v = xr[t + u * TPB];
                cc += fabsf(v.x) > mid; cc += fabsf(v.y) > mid;
                cc += fabsf(v.z) > mid; cc += fabsf(v.w) > mid;
            }
            unsigned r = __reduce_add_sync(0xFFFFFFFFu, (unsigned)cc);
            if (lane == 0) s_w[wid] = r;
            __syncthreads();
            unsigned tot = 0;
            #pragma unroll
            for (int w = 0; w < NWARP; w++) tot += s_w[w];
            __syncthreads();
            if ((int)tot >= KSEL) { lo = mid; cLo = (int)tot; }
            else                  { hi = mid; cHi = (int)tot; }
            guard++;
        }
        if (t == 0) s_cnt = 0;
        __syncthreads();
        #pragma unroll
        for (int u = 0; u < 4; u++) {
            float4 v = xr[t + u * TPB];
            #define TG2(e) { float av = fabsf(e); \
                             if (av > lo && av <= hi) { int id = atomicAdd(&s_cnt, 1); \
                                 if (id < MAXC) s_memb[id] = av; } }
            TG2(v.x) TG2(v.y) TG2(v.z) TG2(v.w)
            #undef TG2
        }
        nd = KSEL - cHi;
    }
    __syncthreads();                                   // B4

    // ---- exact select: nd-th largest among c members (typically c ~ 2-4) ----
    const int c = min(s_cnt, MAXC);
    for (int j = t; j < c; j += TPB) {
        float vj = s_memb[j];
        int gt = 0, ge = 0;
        for (int i = 0; i < c; i++) {
            float vi = s_memb[i];
            gt += vi > vj;
            ge += vi >= vj;
        }
        if (gt < nd && nd <= ge) s_thr = vj;           // matching writers write same value
    }
    __syncthreads();                                   // B5

    const float thr   = s_thr;
    const float bias5 = -5.0f * thr;

    // ---- fused epilogue: re-read row (L1 hit), out = x*(0.5+0.5*tanh(5(|x|-thr))) ----
    #pragma unroll
    for (int u = 0; u < 4; u++) {
        float4 v = xr[t + u * TPB];
        float4 o;
        #define MK(dst, xv) { float z = fmaf(5.0f, fabsf(xv), bias5); float th; \
                              asm("tanh.approx.f32 %0, %1;" : "=f"(th) : "f"(z)); \
                              dst = (xv) * fmaf(0.5f, th, 0.5f); }
        MK(o.x, v.x) MK(o.y, v.y) MK(o.z, v.z) MK(o.w, v.w)
        #undef MK
        orow[t + u * TPB] = o;
    }
}

extern "C" void kernel_launch(void* const* d_in, const int* in_sizes, int n_in,
                              void* d_out, int out_size) {
    const float* x = (const float*)d_in[0];
    float* out = (float*)d_out;
    const int rows = in_sizes[0] / DIM;   // 4 * 2048 = 8192 rows
    sparsify_kernel<<<rows, TPB>>>(x, out);
}